// round 1
// baseline (speedup 1.0000x reference)
#include <cuda_runtime.h>

#define NN   8192
#define DIN  128
#define BI   64
#define JT   32
#define NCH  (NN / JT)
#define QSTRIDE 36          // 32 + 4 pad, keeps float4 alignment, kills bank conflicts
#define HSTRIDE 132
#define WSTRIDE 130
#define THREADS 256

typedef unsigned long long ull;

__device__ __forceinline__ void ffma2(ull& acc, ull q, ull x) {
    asm volatile("fma.rn.f32x2 %0, %1, %2, %0;" : "+l"(acc) : "l"(q), "l"(x));
}
__device__ __forceinline__ ull rep2(float v) {
    ull r; asm("mov.b64 %0, {%1, %1};" : "=l"(r) : "f"(v)); return r;
}
__device__ __forceinline__ ull pack2(float lo, float hi) {
    ull r; asm("mov.b64 %0, {%1, %2};" : "=l"(r) : "f"(lo), "f"(hi)); return r;
}
__device__ __forceinline__ float2 unp2(ull v) {
    float2 r; asm("mov.b64 {%0, %1}, %2;" : "=f"(r.x), "=f"(r.y) : "l"(v)); return r;
}

__global__ void __launch_bounds__(THREADS, 1)
ggd_kernel(const float* __restrict__ theta,
           const float* __restrict__ T,      // [4][8192][8192]
           const float* __restrict__ x,      // [8192][128]
           const float* __restrict__ a,      // [8192][8192]
           const float* __restrict__ alpha,  // [128]
           const float* __restrict__ W,      // [128][128]
           const float* __restrict__ bias,   // [128]
           float* __restrict__ out)          // [8192][128]
{
    extern __shared__ float smem[];
    float* qb = smem;                        // [2][BI][QSTRIDE]
    float* xb = smem + 2 * BI * QSTRIDE;     // [2][JT][DIN]

    const int tid = threadIdx.x;
    const int ti  = tid >> 4;                // 0..15 (i-group)
    const int td  = tid & 15;                // 0..15 (d-group)
    const int i0  = blockIdx.x * BI;

    const float th0 = theta[0], th1 = theta[1], th2 = theta[2], th3 = theta[3];

    // q staging: thread -> (row, two float4 columns of the 32-wide j chunk)
    const int qrow = tid >> 2;               // 0..63
    const int qj4  = tid & 3;                // float4 col; g adds +4
    const size_t SLICE = (size_t)NN * NN;
    const float* Trow = T + (size_t)(i0 + qrow) * NN;
    const float* Arow = a + (size_t)(i0 + qrow) * NN;

    float4 sT[2][4], sA[2], sX[4];

    auto LOAD = [&](int c) {
        const int j0 = c * JT;
        #pragma unroll
        for (int g = 0; g < 2; ++g) {
            const float* p = Trow + j0 + (qj4 + 4 * g) * 4;
            sT[g][0] = __ldcs((const float4*)(p));
            sT[g][1] = __ldcs((const float4*)(p + SLICE));
            sT[g][2] = __ldcs((const float4*)(p + 2 * SLICE));
            sT[g][3] = __ldcs((const float4*)(p + 3 * SLICE));
            sA[g]    = __ldcs((const float4*)(Arow + j0 + (qj4 + 4 * g) * 4));
        }
        #pragma unroll
        for (int s = 0; s < 4; ++s) {
            const int f = tid + THREADS * s;   // 0..1023
            sX[s] = __ldg((const float4*)(x + (size_t)(j0 + (f >> 5)) * DIN + (f & 31) * 4));
        }
    };

    auto STORE = [&](int buf) {
        float* qd = qb + buf * (BI * QSTRIDE);
        #pragma unroll
        for (int g = 0; g < 2; ++g) {
            const float4 t0 = sT[g][0], t1 = sT[g][1], t2 = sT[g][2], t3 = sT[g][3];
            const float4 av = sA[g];
            float4 q;
            q.x = av.x * (th0 * t0.x + th1 * t1.x + th2 * t2.x + th3 * t3.x);
            q.y = av.y * (th0 * t0.y + th1 * t1.y + th2 * t2.y + th3 * t3.y);
            q.z = av.z * (th0 * t0.z + th1 * t1.z + th2 * t2.z + th3 * t3.z);
            q.w = av.w * (th0 * t0.w + th1 * t1.w + th2 * t2.w + th3 * t3.w);
            *(float4*)(qd + qrow * QSTRIDE + (qj4 + 4 * g) * 4) = q;
        }
        float* xd = xb + buf * (JT * DIN);
        #pragma unroll
        for (int s = 0; s < 4; ++s) {
            const int f = tid + THREADS * s;
            *(float4*)(xd + (f >> 5) * DIN + (f & 31) * 4) = sX[s];
        }
    };

    ull acc[4][4];
    #pragma unroll
    for (int r = 0; r < 4; ++r)
        #pragma unroll
        for (int c2 = 0; c2 < 4; ++c2) acc[r][c2] = 0ull;

    LOAD(0);
    STORE(0);
    __syncthreads();

    for (int ch = 0; ch < NCH; ++ch) {
        const int buf = ch & 1;
        if (ch + 1 < NCH) LOAD(ch + 1);      // LDGs in flight during compute

        const float* qs = qb + buf * (BI * QSTRIDE) + (ti * 4) * QSTRIDE;
        const float* xs = xb + buf * (JT * DIN) + 2 * td;

        #pragma unroll
        for (int j4 = 0; j4 < JT / 4; ++j4) {
            float qv[4][4];
            #pragma unroll
            for (int r = 0; r < 4; ++r) {
                const float4 t = *(const float4*)(qs + r * QSTRIDE + j4 * 4);
                qv[r][0] = t.x; qv[r][1] = t.y; qv[r][2] = t.z; qv[r][3] = t.w;
            }
            #pragma unroll
            for (int jj = 0; jj < 4; ++jj) {
                ull xv[4];
                #pragma unroll
                for (int c2 = 0; c2 < 4; ++c2)
                    xv[c2] = *(const ull*)(xs + (j4 * 4 + jj) * DIN + 32 * c2);
                #pragma unroll
                for (int r = 0; r < 4; ++r) {
                    const ull q2 = rep2(qv[r][jj]);
                    #pragma unroll
                    for (int c2 = 0; c2 < 4; ++c2)
                        ffma2(acc[r][c2], q2, xv[c2]);
                }
            }
        }

        if (ch + 1 < NCH) STORE(buf ^ 1);
        __syncthreads();
    }

    // ---------------- fused epilogue: PReLU then @ W^T + b ----------------
    float* hs = smem;                    // [BI][HSTRIDE]
    float* wt = smem + BI * HSTRIDE;     // [DIN][WSTRIDE] (W transposed)

    #pragma unroll
    for (int c2 = 0; c2 < 4; ++c2) {
        const int d0 = 2 * (td + 16 * c2);
        const float a0 = alpha[d0], a1 = alpha[d0 + 1];
        #pragma unroll
        for (int r = 0; r < 4; ++r) {
            float2 h = unp2(acc[r][c2]);
            h.x = h.x > 0.0f ? h.x : a0 * h.x;
            h.y = h.y > 0.0f ? h.y : a1 * h.y;
            *(float2*)(hs + (ti * 4 + r) * HSTRIDE + d0) = h;
        }
    }
    for (int idx = tid; idx < DIN * DIN; idx += THREADS) {
        const int din = idx >> 7, dof = idx & 127;
        wt[din * WSTRIDE + dof] = __ldg(W + dof * DIN + din);
    }
    __syncthreads();

    ull oacc[4][4];
    #pragma unroll
    for (int c2 = 0; c2 < 4; ++c2) {
        const int d0 = 2 * (td + 16 * c2);
        const float2 bb = *(const float2*)(bias + d0);
        const ull bv = pack2(bb.x, bb.y);
        #pragma unroll
        for (int r = 0; r < 4; ++r) oacc[r][c2] = bv;
    }
    #pragma unroll 4
    for (int din = 0; din < DIN; ++din) {
        ull wv[4];
        #pragma unroll
        for (int c2 = 0; c2 < 4; ++c2)
            wv[c2] = *(const ull*)(wt + din * WSTRIDE + 2 * (td + 16 * c2));
        #pragma unroll
        for (int r = 0; r < 4; ++r) {
            const ull h2 = rep2(hs[(ti * 4 + r) * HSTRIDE + din]);
            #pragma unroll
            for (int c2 = 0; c2 < 4; ++c2) ffma2(oacc[r][c2], h2, wv[c2]);
        }
    }
    #pragma unroll
    for (int r = 0; r < 4; ++r) {
        float* orow = out + (size_t)(i0 + ti * 4 + r) * DIN;
        #pragma unroll
        for (int c2 = 0; c2 < 4; ++c2) {
            const float2 o = unp2(oacc[r][c2]);
            *(float2*)(orow + 2 * (td + 16 * c2)) = o;
        }
    }
}

extern "C" void kernel_launch(void* const* d_in, const int* in_sizes, int n_in,
                              void* d_out, int out_size) {
    const float* theta = (const float*)d_in[0];
    const float* T     = (const float*)d_in[1];
    const float* x     = (const float*)d_in[2];
    const float* a     = (const float*)d_in[3];
    const float* alpha = (const float*)d_in[4];
    const float* W     = (const float*)d_in[5];
    const float* b     = (const float*)d_in[6];
    float* out = (float*)d_out;

    const int smem_main = (2 * BI * QSTRIDE + 2 * JT * DIN) * (int)sizeof(float);
    const int smem_epi  = (BI * HSTRIDE + DIN * WSTRIDE) * (int)sizeof(float);
    const int smem_bytes = smem_main > smem_epi ? smem_main : smem_epi;   // 100352

    cudaFuncSetAttribute(ggd_kernel, cudaFuncAttributeMaxDynamicSharedMemorySize, smem_bytes);
    ggd_kernel<<<NN / BI, THREADS, smem_bytes>>>(theta, T, x, a, alpha, W, b, out);
}

// round 6
// speedup vs baseline: 1.6786x; 1.6786x over previous
#include <cuda_runtime.h>
#include <cstdint>

#define NN   8192
#define DIN  128
#define BM   64
#define KC   32
#define NCH  (NN / KC)
#define THREADS 256
#define GRID (NN / BM)

#define ASTR 36                    // A tile row stride (floats): banks (4r+c)%32 distinct
#define BSTR 136                   // B tile row stride (floats): banks (8k+n)%32 distinct
#define A_ELEMS (BM * ASTR)        // 2304 floats
#define B_ELEMS (KC * BSTR)        // 4352 floats
#define STAGE_FLOATS (A_ELEMS + B_ELEMS)   // 6656 floats / 26624 B per stage
#define HSTRIDE 132
#define WSTRIDE 130
#define SMEM_BYTES 100352          // max(2 stages = 53248, epilogue hs+wt = 100352)

typedef unsigned long long ull;

// ---------------- helpers ----------------
__device__ __forceinline__ uint32_t cvt_tf32(float v) {
    uint32_t r; asm("cvt.rna.tf32.f32 %0, %1;" : "=r"(r) : "f"(v)); return r;
}
__device__ __forceinline__ void mma_tf32(float* d, const uint32_t* a, uint32_t b0, uint32_t b1) {
    asm volatile(
        "mma.sync.aligned.m16n8k8.row.col.f32.tf32.tf32.f32 "
        "{%0,%1,%2,%3}, {%4,%5,%6,%7}, {%8,%9}, {%0,%1,%2,%3};"
        : "+f"(d[0]), "+f"(d[1]), "+f"(d[2]), "+f"(d[3])
        : "r"(a[0]), "r"(a[1]), "r"(a[2]), "r"(a[3]), "r"(b0), "r"(b1));
}
__device__ __forceinline__ void ffma2(ull& acc, ull q, ull x) {
    asm volatile("fma.rn.f32x2 %0, %1, %2, %0;" : "+l"(acc) : "l"(q), "l"(x));
}
__device__ __forceinline__ ull rep2(float v) {
    ull r; asm("mov.b64 %0, {%1, %1};" : "=l"(r) : "f"(v)); return r;
}
__device__ __forceinline__ ull pack2(float lo, float hi) {
    ull r; asm("mov.b64 %0, {%1, %2};" : "=l"(r) : "f"(lo), "f"(hi)); return r;
}
__device__ __forceinline__ float2 unp2(ull v) {
    float2 r; asm("mov.b64 {%0, %1}, %2;" : "=f"(r.x), "=f"(r.y) : "l"(v)); return r;
}

__global__ void __launch_bounds__(THREADS, 1)
ggd_kernel(const float* __restrict__ theta,
           const float* __restrict__ T,      // [4][8192][8192]
           const float* __restrict__ x,      // [8192][128]
           const float* __restrict__ a,      // [8192][8192]
           const float* __restrict__ alpha,  // [128]
           const float* __restrict__ W,      // [128][128]
           const float* __restrict__ bias,   // [128]
           float* __restrict__ out)          // [8192][128]
{
    extern __shared__ float smf[];
    const int tid  = threadIdx.x;
    const int lane = tid & 31;
    const int wid  = tid >> 5;
    const int wm   = wid & 3;          // warp m-tile (16 rows each)
    const int wn   = wid >> 2;         // warp n-half (64 cols each)
    const int i0   = blockIdx.x * BM;

    const float th0 = theta[0], th1 = theta[1], th2 = theta[2], th3 = theta[3];

    // ---- staging maps ----
    const int qrow = tid >> 2;         // 0..63
    const int qc4  = tid & 3;          // float4 col; g adds +4
    const size_t SLICE = (size_t)NN * NN;
    const float* Tr = T + (size_t)(i0 + qrow) * NN;
    const float* Ar = a + (size_t)(i0 + qrow) * NN;
    const int xj  = tid >> 3;          // 0..31 (k row of B tile)
    const int xc4 = tid & 7;           // float4 col; it adds +8

    float4 rT[2][4], rA[2], rX[4];

    auto LOAD = [&](int ch) {
        const int j0 = ch * KC;
        #pragma unroll
        for (int g = 0; g < 2; ++g) {
            const float* p = Tr + j0 + (qc4 + 4 * g) * 4;
            rT[g][0] = __ldcs((const float4*)(p));
            rT[g][1] = __ldcs((const float4*)(p + SLICE));
            rT[g][2] = __ldcs((const float4*)(p + 2 * SLICE));
            rT[g][3] = __ldcs((const float4*)(p + 3 * SLICE));
            rA[g]    = __ldcs((const float4*)(Ar + j0 + (qc4 + 4 * g) * 4));
        }
        #pragma unroll
        for (int it = 0; it < 4; ++it)
            rX[it] = __ldg((const float4*)(x + (size_t)(j0 + xj) * DIN + (xc4 + 8 * it) * 4));
    };

    auto STORE = [&](int s) {
        uint32_t* A = (uint32_t*)(smf + s * STAGE_FLOATS);
        uint32_t* B = (uint32_t*)(smf + s * STAGE_FLOATS + A_ELEMS);
        #pragma unroll
        for (int g = 0; g < 2; ++g) {
            const float4 t0 = rT[g][0], t1 = rT[g][1], t2 = rT[g][2], t3 = rT[g][3];
            const float4 av = rA[g];
            uint4 q;
            q.x = cvt_tf32(av.x * (th0 * t0.x + th1 * t1.x + th2 * t2.x + th3 * t3.x));
            q.y = cvt_tf32(av.y * (th0 * t0.y + th1 * t1.y + th2 * t2.y + th3 * t3.y));
            q.z = cvt_tf32(av.z * (th0 * t0.z + th1 * t1.z + th2 * t2.z + th3 * t3.z));
            q.w = cvt_tf32(av.w * (th0 * t0.w + th1 * t1.w + th2 * t2.w + th3 * t3.w));
            *(uint4*)(A + qrow * ASTR + (qc4 + 4 * g) * 4) = q;
        }
        #pragma unroll
        for (int it = 0; it < 4; ++it) {
            uint4 xv;
            xv.x = cvt_tf32(rX[it].x);
            xv.y = cvt_tf32(rX[it].y);
            xv.z = cvt_tf32(rX[it].z);
            xv.w = cvt_tf32(rX[it].w);
            *(uint4*)(B + xj * BSTR + (xc4 + 8 * it) * 4) = xv;
        }
    };

    // ---- fragment base offsets (stage-local float indices) ----
    const int abase = (16 * wm + (lane >> 2)) * ASTR + (lane & 3);
    const int bbase = (lane & 3) * BSTR + 64 * wn + (lane >> 2);

    float acc[8][4];
    #pragma unroll
    for (int nt = 0; nt < 8; ++nt)
        #pragma unroll
        for (int c = 0; c < 4; ++c) acc[nt][c] = 0.0f;

    LOAD(0);
    STORE(0);
    __syncthreads();

    for (int ch = 0; ch < NCH; ++ch) {
        const int s = ch & 1;
        if (ch + 1 < NCH) LOAD(ch + 1);          // LDGs in flight during MMA

        const uint32_t* As = (const uint32_t*)(smf + s * STAGE_FLOATS);
        const uint32_t* Bs = (const uint32_t*)(smf + s * STAGE_FLOATS + A_ELEMS);
        #pragma unroll
        for (int ks = 0; ks < 4; ++ks) {
            uint32_t af[4];
            af[0] = As[abase + 8 * ks];
            af[1] = As[abase + 8 * ks + 8 * ASTR];
            af[2] = As[abase + 8 * ks + 4];
            af[3] = As[abase + 8 * ks + 8 * ASTR + 4];
            #pragma unroll
            for (int nt = 0; nt < 8; ++nt) {
                const uint32_t b0 = Bs[bbase + ks * 8 * BSTR + 8 * nt];
                const uint32_t b1 = Bs[bbase + ks * 8 * BSTR + 8 * nt + 4 * BSTR];
                mma_tf32(acc[nt], af, b0, b1);
            }
        }

        if (ch + 1 < NCH) STORE(s ^ 1);
        __syncthreads();
    }

    // ---------------- epilogue: PReLU -> hs, then @ W^T + b (fp32) ----------------
    float* hs = smf;                     // [BM][HSTRIDE]
    float* wt = smf + BM * HSTRIDE;      // [DIN][WSTRIDE]

    {
        const int r0 = 16 * wm + (lane >> 2);
        #pragma unroll
        for (int nt = 0; nt < 8; ++nt) {
            const int col = 64 * wn + 8 * nt + 2 * (lane & 3);
            const float a0 = __ldg(alpha + col), a1 = __ldg(alpha + col + 1);
            float2 h0, h1;
            h0.x = acc[nt][0] > 0.0f ? acc[nt][0] : a0 * acc[nt][0];
            h0.y = acc[nt][1] > 0.0f ? acc[nt][1] : a1 * acc[nt][1];
            h1.x = acc[nt][2] > 0.0f ? acc[nt][2] : a0 * acc[nt][2];
            h1.y = acc[nt][3] > 0.0f ? acc[nt][3] : a1 * acc[nt][3];
            *(float2*)(hs + r0 * HSTRIDE + col)       = h0;
            *(float2*)(hs + (r0 + 8) * HSTRIDE + col) = h1;
        }
    }
    for (int idx = tid; idx < DIN * DIN; idx += THREADS) {
        const int din = idx >> 7, dof = idx & 127;
        wt[din * WSTRIDE + dof] = __ldg(W + dof * DIN + din);
    }
    __syncthreads();

    const int ti = tid >> 4;             // 0..15 (4 rows each)
    const int td = tid & 15;             // 0..15 (2 cols * 4 groups)
    ull oacc[4][4];
    #pragma unroll
    for (int c2 = 0; c2 < 4; ++c2) {
        const int d0 = 2 * (td + 16 * c2);
        const float2 bb = *(const float2*)(bias + d0);
        const ull bv = pack2(bb.x, bb.y);
        #pragma unroll
        for (int r = 0; r < 4; ++r) oacc[r][c2] = bv;
    }
    #pragma unroll 4
    for (int din = 0; din < DIN; ++din) {
        ull wv[4];
        #pragma unroll
        for (int c2 = 0; c2 < 4; ++c2)
            wv[c2] = *(const ull*)(wt + din * WSTRIDE + 2 * (td + 16 * c2));
        #pragma unroll
        for (int r = 0; r < 4; ++r) {
            const ull h2 = rep2(hs[(ti * 4 + r) * HSTRIDE + din]);
            #pragma unroll
            for (int c2 = 0; c2 < 4; ++c2) ffma2(oacc[r][c2], h2, wv[c2]);
        }
    }
    #pragma unroll
    for (int r = 0; r < 4; ++r) {
        float* orow = out + (size_t)(i0 + ti * 4 + r) * DIN;
        #pragma unroll
        for (int c2 = 0; c2 < 4; ++c2) {
            const float2 o = unp2(oacc[r][c2]);
            *(float2*)(orow + 2 * (td + 16 * c2)) = o;
        }
    }
}

extern "C" void kernel_launch(void* const* d_in, const int* in_sizes, int n_in,
                              void* d_out, int out_size) {
    const float* theta = (const float*)d_in[0];
    const float* T     = (const float*)d_in[1];
    const float* x     = (const float*)d_in[2];
    const float* a     = (const float*)d_in[3];
    const float* alpha = (const float*)d_in[4];
    const float* W     = (const float*)d_in[5];
    const float* b     = (const float*)d_in[6];
    float* out = (float*)d_out;

    cudaFuncSetAttribute(ggd_kernel, cudaFuncAttributeMaxDynamicSharedMemorySize, SMEM_BYTES);
    ggd_kernel<<<GRID, THREADS, SMEM_BYTES>>>(theta, T, x, a, alpha, W, b, out);
}

// round 9
// speedup vs baseline: 2.0166x; 1.2014x over previous
#include <cuda_runtime.h>
#include <cstdint>

#define NN   8192
#define DIN  128
#define BM   64
#define KC   32
#define NCH  (NN / KC)
#define THREADS 256
#define GRID (NN / BM)

#define TSTR 36                          // raw T/a + A-tile row stride (floats)
#define XSTR 136                         // x B-tile row stride (floats)
#define STG_T     (BM * TSTR)            // 2304 floats per T array
#define STG_AOFF  (4 * STG_T)            // 9216
#define STG_XOFF  (5 * STG_T)            // 11520
#define STG_FLOATS (STG_XOFF + KC * XSTR)   // 15872
#define ATILE_OFF (3 * STG_FLOATS)       // 47616
#define SMEM_FLOATS (ATILE_OFF + BM * TSTR) // 49920
#define SMEM_BYTES (SMEM_FLOATS * 4)     // 199680

#define HSTRIDE 132
#define WSTRIDE 130

typedef unsigned long long ull;

// ---------------- helpers ----------------
__device__ __forceinline__ uint32_t smem_u32(const void* p) {
    uint32_t r;
    asm("{ .reg .u64 t; cvta.to.shared.u64 t, %1; cvt.u32.u64 %0, t; }" : "=r"(r) : "l"(p));
    return r;
}
__device__ __forceinline__ void cpasync16(uint32_t dst, const void* src) {
    asm volatile("cp.async.cg.shared.global [%0], [%1], 16;" :: "r"(dst), "l"(src));
}
#define CP_COMMIT() asm volatile("cp.async.commit_group;" ::: "memory")
#define CP_WAIT(n)  asm volatile("cp.async.wait_group %0;" :: "n"(n) : "memory")

__device__ __forceinline__ uint32_t cvt_tf32(float v) {
    uint32_t r; asm("cvt.rna.tf32.f32 %0, %1;" : "=r"(r) : "f"(v)); return r;
}
__device__ __forceinline__ void mma_tf32(float* d, const uint32_t* a, uint32_t b0, uint32_t b1) {
    asm volatile(
        "mma.sync.aligned.m16n8k8.row.col.f32.tf32.tf32.f32 "
        "{%0,%1,%2,%3}, {%4,%5,%6,%7}, {%8,%9}, {%0,%1,%2,%3};"
        : "+f"(d[0]), "+f"(d[1]), "+f"(d[2]), "+f"(d[3])
        : "r"(a[0]), "r"(a[1]), "r"(a[2]), "r"(a[3]), "r"(b0), "r"(b1));
}
__device__ __forceinline__ void ffma2(ull& acc, ull q, ull x) {
    asm volatile("fma.rn.f32x2 %0, %1, %2, %0;" : "+l"(acc) : "l"(q), "l"(x));
}
__device__ __forceinline__ ull rep2(float v) {
    ull r; asm("mov.b64 %0, {%1, %1};" : "=l"(r) : "f"(v)); return r;
}
__device__ __forceinline__ ull pack2(float lo, float hi) {
    ull r; asm("mov.b64 %0, {%1, %2};" : "=l"(r) : "f"(lo), "f"(hi)); return r;
}
__device__ __forceinline__ float2 unp2(ull v) {
    float2 r; asm("mov.b64 {%0, %1}, %2;" : "=f"(r.x), "=f"(r.y) : "l"(v)); return r;
}

__global__ void __launch_bounds__(THREADS, 1)
ggd_kernel(const float* __restrict__ theta,
           const float* __restrict__ T,      // [4][8192][8192]
           const float* __restrict__ x,      // [8192][128]
           const float* __restrict__ a,      // [8192][8192]
           const float* __restrict__ alpha,  // [128]
           const float* __restrict__ W,      // [128][128]
           const float* __restrict__ bias,   // [128]
           float* __restrict__ out)          // [8192][128]
{
    extern __shared__ float smf[];
    const uint32_t sb = smem_u32(smf);
    const int tid  = threadIdx.x;
    const int lane = tid & 31;
    const int wid  = tid >> 5;
    const int wm   = wid & 1;          // 32-row half
    const int wn   = wid >> 1;         // 32-col group
    const int i0   = blockIdx.x * BM;

    const float th0 = theta[0], th1 = theta[1], th2 = theta[2], th3 = theta[3];

    // ---- cp.async staging maps ----
    const int gcol  = tid & 7;         // 16B granule within 128B T/a row seg
    const int growb = tid >> 3;        // 0..31 (row; +32 for rr=1)
    const size_t SLICE = (size_t)NN * NN;
    const float* gTA[5];
    #pragma unroll
    for (int k = 0; k < 4; ++k)
        gTA[k] = T + k * SLICE + (size_t)(i0 + growb) * NN + gcol * 4;
    gTA[4] = a + (size_t)(i0 + growb) * NN + gcol * 4;
    const int xcol = tid & 31;         // 16B granule within 512B x row
    const int xrow = tid >> 5;         // 0..7 (+8*rr)
    const float* gx = x + (size_t)xrow * DIN + xcol * 4;

    auto LOAD = [&](int ch, int s) {
        const int j0 = ch * KC;
        const uint32_t sbase = sb + (uint32_t)(s * STG_FLOATS) * 4u;
        #pragma unroll
        for (int arr = 0; arr < 5; ++arr)
            #pragma unroll
            for (int rr = 0; rr < 2; ++rr) {
                const uint32_t dst = sbase +
                    (uint32_t)(arr * STG_T + (growb + 32 * rr) * TSTR + gcol * 4) * 4u;
                cpasync16(dst, gTA[arr] + (size_t)(32 * rr) * NN + j0);
            }
        #pragma unroll
        for (int rr = 0; rr < 4; ++rr) {
            const uint32_t dst = sbase +
                (uint32_t)(STG_XOFF + (xrow + 8 * rr) * XSTR + xcol * 4) * 4u;
            cpasync16(dst, gx + (size_t)(j0 + 8 * rr) * DIN);
        }
        CP_COMMIT();
    };

    // ---- q-build map: 32 distinct rows per warp -> conflict-free LDS.128 ----
    const int qrow = tid & 63;
    const int qc4  = tid >> 6;         // 0..3

    auto QBUILD = [&](int s) {
        const float* st = smf + s * STG_FLOATS;
        float* at = smf + ATILE_OFF;
        #pragma unroll
        for (int g = 0; g < 2; ++g) {
            const int jf = (qc4 + 4 * g) * 4;
            const float4 t0 = *(const float4*)(st + 0 * STG_T + qrow * TSTR + jf);
            const float4 t1 = *(const float4*)(st + 1 * STG_T + qrow * TSTR + jf);
            const float4 t2 = *(const float4*)(st + 2 * STG_T + qrow * TSTR + jf);
            const float4 t3 = *(const float4*)(st + 3 * STG_T + qrow * TSTR + jf);
            const float4 av = *(const float4*)(st + STG_AOFF + qrow * TSTR + jf);
            uint4 q;
            q.x = cvt_tf32(av.x * (th0 * t0.x + th1 * t1.x + th2 * t2.x + th3 * t3.x));
            q.y = cvt_tf32(av.y * (th0 * t0.y + th1 * t1.y + th2 * t2.y + th3 * t3.y));
            q.z = cvt_tf32(av.z * (th0 * t0.z + th1 * t1.z + th2 * t2.z + th3 * t3.z));
            q.w = cvt_tf32(av.w * (th0 * t0.w + th1 * t1.w + th2 * t2.w + th3 * t3.w));
            *(uint4*)(void*)(at + qrow * TSTR + jf) = q;
        }
    };

    // ---- MMA fragment bases ----
    const int abase = (32 * wm + (lane >> 2)) * TSTR + (lane & 3);
    const int bbase = (lane & 3) * XSTR + 32 * wn + (lane >> 2);

    float acc[2][4][4];
    #pragma unroll
    for (int mt = 0; mt < 2; ++mt)
        #pragma unroll
        for (int nt = 0; nt < 4; ++nt)
            #pragma unroll
            for (int c = 0; c < 4; ++c) acc[mt][nt][c] = 0.0f;

    LOAD(0, 0);
    LOAD(1, 1);

    for (int ch = 0; ch < NCH; ++ch) {
        const int s = ch % 3;
        if (ch + 1 < NCH) CP_WAIT(1); else CP_WAIT(0);
        __syncthreads();                       // stage s visible; MMA(ch-1) done by all
        if (ch + 2 < NCH) LOAD(ch + 2, (ch + 2) % 3);   // refill freed stage (async)
        QBUILD(s);
        __syncthreads();                       // A-tile ready
        {
            const uint32_t* At = (const uint32_t*)(smf + ATILE_OFF);
            const uint32_t* Bs = (const uint32_t*)(smf + s * STG_FLOATS + STG_XOFF);
            #pragma unroll
            for (int ks = 0; ks < 4; ++ks) {
                uint32_t af[2][4];
                #pragma unroll
                for (int mt = 0; mt < 2; ++mt) {
                    const int ab = abase + 16 * mt * TSTR + 8 * ks;
                    af[mt][0] = At[ab];
                    af[mt][1] = At[ab + 8 * TSTR];
                    af[mt][2] = At[ab + 4];
                    af[mt][3] = At[ab + 8 * TSTR + 4];
                }
                #pragma unroll
                for (int nt = 0; nt < 4; ++nt) {
                    const int bb = bbase + 8 * ks * XSTR + 8 * nt;
                    const uint32_t b0 = Bs[bb];
                    const uint32_t b1 = Bs[bb + 4 * XSTR];
                    mma_tf32(acc[0][nt], af[0], b0, b1);
                    mma_tf32(acc[1][nt], af[1], b0, b1);
                }
            }
        }
    }
    __syncthreads();                           // all MMA/LDS done before smem reuse

    // ---------------- epilogue: PReLU -> hs, then @ W^T + b (fp32) ----------------
    float* hs = smf;                     // [BM][HSTRIDE]
    float* wt = smf + BM * HSTRIDE;      // [DIN][WSTRIDE]

    {
        const int r0 = 32 * wm + (lane >> 2);
        #pragma unroll
        for (int mt = 0; mt < 2; ++mt)
            #pragma unroll
            for (int nt = 0; nt < 4; ++nt) {
                const int col = 32 * wn + 8 * nt + 2 * (lane & 3);
                const float a0 = __ldg(alpha + col), a1 = __ldg(alpha + col + 1);
                float2 h0, h1;
                h0.x = acc[mt][nt][0] > 0.0f ? acc[mt][nt][0] : a0 * acc[mt][nt][0];
                h0.y = acc[mt][nt][1] > 0.0f ? acc[mt][nt][1] : a1 * acc[mt][nt][1];
                h1.x = acc[mt][nt][2] > 0.0f ? acc[mt][nt][2] : a0 * acc[mt][nt][2];
                h1.y = acc[mt][nt][3] > 0.0f ? acc[mt][nt][3] : a1 * acc[mt][nt][3];
                *(float2*)(hs + (r0 + 16 * mt) * HSTRIDE + col)     = h0;
                *(float2*)(hs + (r0 + 16 * mt + 8) * HSTRIDE + col) = h1;
            }
    }
    for (int idx = tid; idx < DIN * DIN; idx += THREADS) {
        const int din = idx >> 7, dof = idx & 127;
        wt[din * WSTRIDE + dof] = __ldg(W + dof * DIN + din);
    }
    __syncthreads();

    const int ti = tid >> 4;             // 0..15 (4 rows each)
    const int td = tid & 15;
    ull oacc[4][4];
    #pragma unroll
    for (int c2 = 0; c2 < 4; ++c2) {
        const int d0 = 2 * (td + 16 * c2);
        const float2 bb = *(const float2*)(bias + d0);
        const ull bv = pack2(bb.x, bb.y);
        #pragma unroll
        for (int r = 0; r < 4; ++r) oacc[r][c2] = bv;
    }
    #pragma unroll 4
    for (int din = 0; din < DIN; ++din) {
        ull wv[4];
        #pragma unroll
        for (int c2 = 0; c2 < 4; ++c2)
            wv[c2] = *(const ull*)(wt + din * WSTRIDE + 2 * (td + 16 * c2));
        #pragma unroll
        for (int r = 0; r < 4; ++r) {
            const ull h2 = rep2(hs[(ti * 4 + r) * HSTRIDE + din]);
            #pragma unroll
            for (int c2 = 0; c2 < 4; ++c2) ffma2(oacc[r][c2], h2, wv[c2]);
        }
    }
    #pragma unroll
    for (int r = 0; r < 4; ++r) {
        float* orow = out + (size_t)(i0 + ti * 4 + r) * DIN;
        #pragma unroll
        for (int c2 = 0; c2 < 4; ++c2) {
            const float2 o = unp2(oacc[r][c2]);
            *(float2*)(orow + 2 * (td + 16 * c2)) = o;
        }
    }
}

extern "C" void kernel_launch(void* const* d_in, const int* in_sizes, int n_in,
                              void* d_out, int out_size) {
    const float* theta = (const float*)d_in[0];
    const float* T     = (const float*)d_in[1];
    const float* x     = (const float*)d_in[2];
    const float* a     = (const float*)d_in[3];
    const float* alpha = (const float*)d_in[4];
    const float* W     = (const float*)d_in[5];
    const float* b     = (const float*)d_in[6];
    float* out = (float*)d_out;

    cudaFuncSetAttribute(ggd_kernel, cudaFuncAttributeMaxDynamicSharedMemorySize, SMEM_BYTES);
    ggd_kernel<<<GRID, THREADS, SMEM_BYTES>>>(theta, T, x, a, alpha, W, b, out);
}